// round 1
// baseline (speedup 1.0000x reference)
#include <cuda_runtime.h>
#include <math.h>

// Problem shape (fixed)
#define BDIM 1024
#define PDIM 64
#define CDIM 512

typedef unsigned long long ull;

// ---------------------------------------------------------------------------
// packed f32x2 helpers (sm_103a FFMA2 path — full-rate fp32)
// ---------------------------------------------------------------------------
__device__ __forceinline__ ull pack2(float lo, float hi) {
    ull r;
    asm("mov.b64 %0, {%1, %2};" : "=l"(r) : "f"(lo), "f"(hi));
    return r;
}
__device__ __forceinline__ void unpack2(ull v, float &lo, float &hi) {
    asm("mov.b64 {%0, %1}, %2;" : "=f"(lo), "=f"(hi) : "l"(v));
}
__device__ __forceinline__ void fma2(ull &d, ull a, ull b) {
    asm("fma.rn.f32x2 %0, %1, %2, %0;" : "+l"(d) : "l"(a), "l"(b));
}

// Scratch for the hidden activation h = GELU(x W1^T + b1), same layout as x.
__device__ float g_h[BDIM * PDIM * CDIM];

// ---------------------------------------------------------------------------
// Lane-per-channel batched GEMM.
//   out[b,q,c] = sum_p W[c,q,p] * X[b,p,c] + bias[c,q]   (then epilogue)
// MODE 0: epilogue = exact GELU          (GEMM1)
// MODE 1: epilogue = + resid[b,q,c]      (GEMM2, residual add, writes d_out)
//
// CTA: 32 channels (lane = channel) x 32 batches (8 warps x NB=4).
// Grid: (C/32, B/32) = (16, 32).
// ---------------------------------------------------------------------------
template <int MODE>
__global__ void __launch_bounds__(256, 2)
gemm_kernel(const float* __restrict__ X,
            const float* __restrict__ W,
            const float* __restrict__ bias,
            const float* __restrict__ resid,
            float* __restrict__ Out)
{
    // Weight tile: [q within tile][c][p within tile], p padded to 17 floats.
    // 17 is coprime with 32 -> conflict-free LDS across lanes (stride 17),
    // and STS (p fastest across lanes, stride 1).
    __shared__ float Ws[16][32][17];

    const int lane = threadIdx.x & 31;
    const int warp = threadIdx.x >> 5;
    const int c0   = blockIdx.x * 32;
    const int c    = c0 + lane;
    const int b0   = blockIdx.y * 32 + warp * 4;

    const float* xptr[4];
#pragma unroll
    for (int nb = 0; nb < 4; nb++)
        xptr[nb] = X + (size_t)(b0 + nb) * (PDIM * CDIM) + c;

    for (int q0 = 0; q0 < PDIM; q0 += 16) {
        // Accumulators: 4 batches x 8 packed (q, q+1) pairs. Init with bias
        // pair, which is adjacent in memory: bias[c*64 + q], bias[c*64 + q+1].
        ull acc[4][8];
#pragma unroll
        for (int qh = 0; qh < 8; qh++) {
            ull bp = *(const ull*)(bias + (size_t)c * PDIM + q0 + 2 * qh);
#pragma unroll
            for (int nb = 0; nb < 4; nb++) acc[nb][qh] = bp;
        }

        for (int p0 = 0; p0 < PDIM; p0 += 16) {
            __syncthreads();
            // Cooperative stage of W[c0:c0+32, q0:q0+16, p0:p0+16].
            // i layout: p fastest (gmem-coalesced, 64B rows), then q, then c.
            for (int i = threadIdx.x; i < 16 * 16 * 32; i += 256) {
                int p  = i & 15;
                int q  = (i >> 4) & 15;
                int ct = i >> 8;
                Ws[q][ct][p] =
                    W[(size_t)(c0 + ct) * (PDIM * PDIM) + (size_t)(q0 + q) * PDIM + (p0 + p)];
            }
            __syncthreads();

#pragma unroll
            for (int p = 0; p < 16; p++) {
                ull xv[4];
#pragma unroll
                for (int nb = 0; nb < 4; nb++) {
                    float xs = __ldg(xptr[nb] + (size_t)(p0 + p) * CDIM);
                    xv[nb] = pack2(xs, xs);
                }
#pragma unroll
                for (int qh = 0; qh < 8; qh++) {
                    ull wv = pack2(Ws[2 * qh][lane][p], Ws[2 * qh + 1][lane][p]);
#pragma unroll
                    for (int nb = 0; nb < 4; nb++)
                        fma2(acc[nb][qh], wv, xv[nb]);
                }
            }
        }

        // Epilogue
#pragma unroll
        for (int nb = 0; nb < 4; nb++) {
            int b = b0 + nb;
#pragma unroll
            for (int qh = 0; qh < 8; qh++) {
                float v0, v1;
                unpack2(acc[nb][qh], v0, v1);
                size_t o = (size_t)b * (PDIM * CDIM) + (size_t)(q0 + 2 * qh) * CDIM + c;
                if (MODE == 0) {
                    // exact GELU: 0.5 x (1 + erf(x / sqrt(2)))
                    v0 = 0.5f * v0 * (1.0f + erff(v0 * 0.70710678118654752f));
                    v1 = 0.5f * v1 * (1.0f + erff(v1 * 0.70710678118654752f));
                } else {
                    v0 += resid[o];
                    v1 += resid[o + CDIM];
                }
                Out[o]        = v0;
                Out[o + CDIM] = v1;
            }
        }
    }
}

// ---------------------------------------------------------------------------
// In-place LayerNorm over the channel dim (512, contiguous).
// One warp per (b, p) row; row lives entirely in registers.
// ---------------------------------------------------------------------------
__global__ void __launch_bounds__(256)
ln_kernel(float* __restrict__ io,
          const float* __restrict__ gamma,
          const float* __restrict__ beta)
{
    int row  = blockIdx.x * 8 + (threadIdx.x >> 5);
    int lane = threadIdx.x & 31;
    float* base = io + (size_t)row * CDIM;

    float4 v[4];
    float s = 0.f, ss = 0.f;
#pragma unroll
    for (int k = 0; k < 4; k++) {
        v[k] = *(const float4*)(base + k * 128 + lane * 4);
        s  += v[k].x + v[k].y + v[k].z + v[k].w;
        ss += v[k].x * v[k].x + v[k].y * v[k].y + v[k].z * v[k].z + v[k].w * v[k].w;
    }
#pragma unroll
    for (int o = 16; o; o >>= 1) {
        s  += __shfl_xor_sync(0xffffffffu, s, o);
        ss += __shfl_xor_sync(0xffffffffu, ss, o);
    }
    const float inv_n = 1.0f / 512.0f;
    float mean = s * inv_n;
    float var  = ss * inv_n - mean * mean;
    float inv  = rsqrtf(var + 1e-5f);

#pragma unroll
    for (int k = 0; k < 4; k++) {
        float4 g = *(const float4*)(gamma + k * 128 + lane * 4);
        float4 bt = *(const float4*)(beta + k * 128 + lane * 4);
        float4 o4;
        o4.x = (v[k].x - mean) * inv * g.x + bt.x;
        o4.y = (v[k].y - mean) * inv * g.y + bt.y;
        o4.z = (v[k].z - mean) * inv * g.z + bt.z;
        o4.w = (v[k].w - mean) * inv * g.w + bt.w;
        *(float4*)(base + k * 128 + lane * 4) = o4;
    }
}

// ---------------------------------------------------------------------------
extern "C" void kernel_launch(void* const* d_in, const int* in_sizes, int n_in,
                              void* d_out, int out_size)
{
    const float* x     = (const float*)d_in[0];
    const float* W1    = (const float*)d_in[1];
    const float* b1    = (const float*)d_in[2];
    const float* W2    = (const float*)d_in[3];
    const float* b2    = (const float*)d_in[4];
    const float* gamma = (const float*)d_in[5];
    const float* beta  = (const float*)d_in[6];
    float* out = (float*)d_out;

    float* hbuf = nullptr;
    cudaGetSymbolAddress((void**)&hbuf, g_h);

    dim3 grid(CDIM / 32, BDIM / 32);  // (16, 32)
    gemm_kernel<0><<<grid, 256>>>(x, W1, b1, nullptr, hbuf);      // h = GELU(xW1+b1)
    gemm_kernel<1><<<grid, 256>>>(hbuf, W2, b2, x, out);          // res = hW2+b2+x
    ln_kernel<<<(BDIM * PDIM) / 8, 256>>>(out, gamma, beta);      // in-place LN
}

// round 4
// speedup vs baseline: 1.6067x; 1.6067x over previous
#include <cuda_runtime.h>
#include <cuda_bf16.h>
#include <math.h>
#include <stdint.h>

#define BDIM 1024
#define PDIM 64
#define CDIM 512

// ---------------------------------------------------------------------------
// Scratch (device globals; no allocations allowed)
// ---------------------------------------------------------------------------
__device__ __align__(128) __nv_bfloat16 g_xh[(size_t)CDIM * BDIM * PDIM];
__device__ __align__(128) __nv_bfloat16 g_xl[(size_t)CDIM * BDIM * PDIM];
__device__ __align__(128) __nv_bfloat16 g_hh[(size_t)CDIM * BDIM * PDIM];
__device__ __align__(128) __nv_bfloat16 g_hl[(size_t)CDIM * BDIM * PDIM];
__device__ __align__(128) float         g_o [(size_t)CDIM * BDIM * PDIM];
__device__ __align__(128) __nv_bfloat16 g_w1h[(size_t)CDIM * PDIM * PDIM];
__device__ __align__(128) __nv_bfloat16 g_w1l[(size_t)CDIM * PDIM * PDIM];
__device__ __align__(128) __nv_bfloat16 g_w2h[(size_t)CDIM * PDIM * PDIM];
__device__ __align__(128) __nv_bfloat16 g_w2l[(size_t)CDIM * PDIM * PDIM];

// ---------------------------------------------------------------------------
// mma.sync / ldmatrix helpers (baseline PTX — compiles for compute_103)
// ---------------------------------------------------------------------------
__device__ __forceinline__ uint32_t smem_u32(const void* p) {
    uint32_t a;
    asm("{ .reg .u64 t; cvta.to.shared.u64 t, %1; cvt.u32.u64 %0, t; }" : "=r"(a) : "l"(p));
    return a;
}

#define LDM_X4(r, addr)                                                         \
    asm volatile("ldmatrix.sync.aligned.m8n8.x4.shared.b16 {%0,%1,%2,%3}, [%4];"\
        : "=r"((r)[0]), "=r"((r)[1]), "=r"((r)[2]), "=r"((r)[3]) : "r"(addr))

// NON-trans x2: B smem rows are [n][k] with k contiguous -> fragment layout
// lane g*4+t = (n=g, k=2t,2t+1) exactly as mma row.col requires.
#define LDM_X2(r, addr)                                                         \
    asm volatile("ldmatrix.sync.aligned.m8n8.x2.shared.b16 {%0,%1}, [%2];"      \
        : "=r"((r)[0]), "=r"((r)[1]) : "r"(addr))

#define MMA_BF16(c, a, b)                                                       \
    asm volatile("mma.sync.aligned.m16n8k16.row.col.f32.bf16.bf16.f32 "         \
        "{%0,%1,%2,%3}, {%4,%5,%6,%7}, {%8,%9}, {%0,%1,%2,%3};"                 \
        : "+f"((c)[0]), "+f"((c)[1]), "+f"((c)[2]), "+f"((c)[3])                \
        : "r"((a)[0]), "r"((a)[1]), "r"((a)[2]), "r"((a)[3]),                   \
          "r"((b)[0]), "r"((b)[1]))

// ---------------------------------------------------------------------------
// Kernel 1: split W -> bf16 hi/lo (elementwise)
// ---------------------------------------------------------------------------
__global__ void __launch_bounds__(256)
wsplit_kernel(const float* __restrict__ W1, const float* __restrict__ W2,
              __nv_bfloat16* __restrict__ w1h, __nv_bfloat16* __restrict__ w1l,
              __nv_bfloat16* __restrict__ w2h, __nv_bfloat16* __restrict__ w2l)
{
    size_t i = (size_t)blockIdx.x * 256 + threadIdx.x;
    float a = W1[i];
    __nv_bfloat16 h = __float2bfloat16(a);
    w1h[i] = h;
    w1l[i] = __float2bfloat16(a - __bfloat162float(h));
    float b = W2[i];
    __nv_bfloat16 h2 = __float2bfloat16(b);
    w2h[i] = h2;
    w2l[i] = __float2bfloat16(b - __bfloat162float(h2));
}

// ---------------------------------------------------------------------------
// Kernel 2: transpose + split  x[b,p,c] -> xh/xl[c,b,p] (bf16)
// ---------------------------------------------------------------------------
__global__ void __launch_bounds__(256)
xsplit_kernel(const float* __restrict__ x,
              __nv_bfloat16* __restrict__ xh, __nv_bfloat16* __restrict__ xl)
{
    __shared__ float sm[32][65];
    const int b = blockIdx.y;
    const int c0 = blockIdx.x * 32;

    for (int i = threadIdx.x; i < 32 * 64; i += 256) {
        int p = i >> 5, cc = i & 31;
        sm[cc][p] = x[((size_t)b * PDIM + p) * CDIM + c0 + cc];
    }
    __syncthreads();

    const int cc = threadIdx.x >> 3;
    const int p0 = (threadIdx.x & 7) * 8;
    __nv_bfloat16 hv[8], lv[8];
#pragma unroll
    for (int i = 0; i < 8; i++) {
        float v = sm[cc][p0 + i];
        hv[i] = __float2bfloat16(v);
        lv[i] = __float2bfloat16(v - __bfloat162float(hv[i]));
    }
    size_t base = ((size_t)(c0 + cc) * BDIM + b) * PDIM + p0;
    *(uint4*)(xh + base) = *(uint4*)hv;
    *(uint4*)(xl + base) = *(uint4*)lv;
}

// ---------------------------------------------------------------------------
// Kernel 3/4: per-channel GEMM via mma.sync bf16 split-3 (fp32-accurate).
//   D[128b, 64q] = Ah·Bh^T + Ah·Bl^T + Al·Bh^T
// A tiles [c][b][p], B = W[c][q][p] (k = p). B fragment loaded with NON-trans
// ldmatrix.x2 (smem rows are n-major, k contiguous).
// MODE 0: epilogue = +bias, exact GELU, split -> outH/outL (bf16)
// MODE 1: epilogue = +bias -> outF (fp32, layout [c][b][q])
// ---------------------------------------------------------------------------
template <int MODE>
__global__ void __launch_bounds__(256)
gemm_ws_kernel(const __nv_bfloat16* __restrict__ Ah_g, const __nv_bfloat16* __restrict__ Al_g,
               const __nv_bfloat16* __restrict__ Bh_g, const __nv_bfloat16* __restrict__ Bl_g,
               const float* __restrict__ bias,
               __nv_bfloat16* __restrict__ outH, __nv_bfloat16* __restrict__ outL,
               float* __restrict__ outF)
{
    extern __shared__ __align__(16) char smem[];
    // byte offsets (row stride 144 = 72 halves everywhere)
    const uint32_t AH = 0, AL = 18432, BH = 36864, BL = 46080, BIAS = 55296;

    const int tid  = threadIdx.x;
    const int warp = tid >> 5;
    const int lane = tid & 31;
    const int b0   = blockIdx.x * 128;
    const int c    = blockIdx.y;

    // ---- stage tiles (gmem rows are 128B; smem rows padded to 144B) ----
    {
        const uint4* sAh = (const uint4*)(Ah_g + ((size_t)c * BDIM + b0) * PDIM);
        const uint4* sAl = (const uint4*)(Al_g + ((size_t)c * BDIM + b0) * PDIM);
        for (int i = tid; i < 1024; i += 256) {           // 128 rows x 8 chunks
            int row = i >> 3, ch = i & 7;
            *(uint4*)(smem + AH + row * 144 + ch * 16) = sAh[i];
            *(uint4*)(smem + AL + row * 144 + ch * 16) = sAl[i];
        }
        const uint4* sBh = (const uint4*)(Bh_g + (size_t)c * PDIM * PDIM);
        const uint4* sBl = (const uint4*)(Bl_g + (size_t)c * PDIM * PDIM);
        for (int i = tid; i < 512; i += 256) {            // 64 rows x 8 chunks
            int row = i >> 3, ch = i & 7;
            *(uint4*)(smem + BH + row * 144 + ch * 16) = sBh[i];
            *(uint4*)(smem + BL + row * 144 + ch * 16) = sBl[i];
        }
        if (tid < 64) ((float*)(smem + BIAS))[tid] = bias[(size_t)c * PDIM + tid];
    }
    __syncthreads();

    // ---- mainloop ----
    float acc[8][4] = {};
    const uint32_t sb = smem_u32(smem);
    // A ldmatrix x4: lanes 0-15 -> rows (k lo 16B), lanes 16-31 -> rows (k hi 16B)
    const uint32_t aAdrH = sb + AH + (uint32_t)(warp * 16 + (lane & 15)) * 144 + (uint32_t)(lane >> 4) * 16;
    const uint32_t aAdrL = aAdrH + (AL - AH);
    // B ldmatrix x2 (non-trans): lanes 0-7 -> n rows @ k-byte 0, lanes 8-15 -> n rows @ k-byte 16
    const uint32_t bAdrH = sb + BH + (uint32_t)(lane & 7) * 144 + (uint32_t)((lane >> 3) & 1) * 16;
    const uint32_t bAdrL = bAdrH + (BL - BH);

#pragma unroll
    for (int kc = 0; kc < 4; kc++) {
        uint32_t ah[4], al[4];
        LDM_X4(ah, aAdrH + kc * 32);
        LDM_X4(al, aAdrL + kc * 32);
#pragma unroll
        for (int n = 0; n < 8; n++) {
            uint32_t bh[2], bl[2];
            LDM_X2(bh, bAdrH + n * 1152 + kc * 32);   // 8 n-rows * 144B = 1152
            LDM_X2(bl, bAdrL + n * 1152 + kc * 32);
            MMA_BF16(acc[n], ah, bh);
            MMA_BF16(acc[n], ah, bl);
            MMA_BF16(acc[n], al, bh);
        }
    }
    __syncthreads();   // everyone done reading tiles; smem reused for epilogue

    const int gid = lane >> 2, tq = lane & 3;
    const int r0 = warp * 16 + gid, r1 = r0 + 8;
    const float* bs = (const float*)(smem + BIAS);

    if (MODE == 0) {
#pragma unroll
        for (int n = 0; n < 8; n++) {
            int q = n * 8 + 2 * tq;
            float v[4];
            v[0] = acc[n][0] + bs[q];
            v[1] = acc[n][1] + bs[q + 1];
            v[2] = acc[n][2] + bs[q];
            v[3] = acc[n][3] + bs[q + 1];
#pragma unroll
            for (int j = 0; j < 4; j++)
                v[j] = 0.5f * v[j] * (1.0f + erff(v[j] * 0.70710678118654752f));
            // split to bf16 hi/lo, pack (q, q+1) pairs into u32
            uint32_t hi[2], lo[2];
#pragma unroll
            for (int half = 0; half < 2; half++) {
                __nv_bfloat16 h0 = __float2bfloat16(v[2 * half]);
                __nv_bfloat16 h1 = __float2bfloat16(v[2 * half + 1]);
                __nv_bfloat16 l0 = __float2bfloat16(v[2 * half] - __bfloat162float(h0));
                __nv_bfloat16 l1 = __float2bfloat16(v[2 * half + 1] - __bfloat162float(h1));
                hi[half] = ((uint32_t)__bfloat16_as_ushort(h1) << 16) | __bfloat16_as_ushort(h0);
                lo[half] = ((uint32_t)__bfloat16_as_ushort(l1) << 16) | __bfloat16_as_ushort(l0);
            }
            int col = (n * 4 + tq) * 4;  // u32 byte col within 128B row payload
            *(uint32_t*)(smem + r0 * 144 + col)      = hi[0];
            *(uint32_t*)(smem + AL + r0 * 144 + col) = lo[0];
            *(uint32_t*)(smem + r1 * 144 + col)      = hi[1];
            *(uint32_t*)(smem + AL + r1 * 144 + col) = lo[1];
        }
        __syncthreads();
        uint4* dH = (uint4*)(outH + ((size_t)c * BDIM + b0) * PDIM);
        uint4* dL = (uint4*)(outL + ((size_t)c * BDIM + b0) * PDIM);
        for (int i = tid; i < 1024; i += 256) {
            int row = i >> 3, ch = i & 7;
            dH[i] = *(uint4*)(smem + row * 144 + ch * 16);
            dL[i] = *(uint4*)(smem + AL + row * 144 + ch * 16);
        }
    } else {
        // fp32 staging rows: stride 272B (68 floats)
#pragma unroll
        for (int n = 0; n < 8; n++) {
            int q = n * 8 + 2 * tq;
            float2 lo2, hi2;
            lo2.x = acc[n][0] + bs[q];
            lo2.y = acc[n][1] + bs[q + 1];
            hi2.x = acc[n][2] + bs[q];
            hi2.y = acc[n][3] + bs[q + 1];
            *(float2*)(smem + r0 * 272 + q * 4) = lo2;
            *(float2*)(smem + r1 * 272 + q * 4) = hi2;
        }
        __syncthreads();
        float* dF = outF + ((size_t)c * BDIM + b0) * PDIM;
        for (int i = tid; i < 2048; i += 256) {
            int row = i >> 4, ch = i & 15;
            *(uint4*)(dF + row * 64 + ch * 4) = *(uint4*)(smem + row * 272 + ch * 16);
        }
    }
}

// ---------------------------------------------------------------------------
// Kernel 5: residual + LayerNorm over channels.
//   out[b,q,c] = LN_c( o[c,b,q] + x[b,q,c] ) * gamma + beta
// ---------------------------------------------------------------------------
__global__ void __launch_bounds__(256)
ln_kernel(const float* __restrict__ o, const float* __restrict__ x,
          const float* __restrict__ gamma, const float* __restrict__ beta,
          float* __restrict__ out)
{
    __shared__ float res[16][517];
    __shared__ float psum[16][17], psqs[16][17];
    __shared__ float pmean[16], pinv[16];

    const int b = blockIdx.y;
    const int q0 = blockIdx.x * 16;
    const size_t xbase = ((size_t)b * PDIM + q0) * CDIM;

    for (int i = threadIdx.x; i < 16 * 512; i += 256) {
        int q = i >> 9, cc = i & 511;
        res[q][cc] = x[xbase + (size_t)q * CDIM + cc];
    }
    __syncthreads();

    {
        const int q = threadIdx.x & 15, cg = threadIdx.x >> 4;
        const size_t orow = (size_t)b * PDIM + q0 + q;
        float s = 0.f, ss = 0.f;
#pragma unroll 4
        for (int j = 0; j < 32; j++) {
            int cc = cg * 32 + j;
            float v = res[q][cc] + o[(size_t)cc * (BDIM * PDIM) + orow];
            res[q][cc] = v;
            s += v; ss += v * v;
        }
        psum[q][cg] = s; psqs[q][cg] = ss;
    }
    __syncthreads();

    if (threadIdx.x < 16) {
        float S = 0.f, SS = 0.f;
#pragma unroll
        for (int g = 0; g < 16; g++) { S += psum[threadIdx.x][g]; SS += psqs[threadIdx.x][g]; }
        float mean = S * (1.0f / 512.0f);
        float var  = SS * (1.0f / 512.0f) - mean * mean;
        pmean[threadIdx.x] = mean;
        pinv[threadIdx.x]  = rsqrtf(var + 1e-5f);
    }
    __syncthreads();

    for (int i = threadIdx.x; i < 16 * 512; i += 256) {
        int q = i >> 9, cc = i & 511;
        out[xbase + (size_t)q * CDIM + cc] =
            (res[q][cc] - pmean[q]) * pinv[q] * gamma[cc] + beta[cc];
    }
}

// ---------------------------------------------------------------------------
extern "C" void kernel_launch(void* const* d_in, const int* in_sizes, int n_in,
                              void* d_out, int out_size)
{
    const float* x     = (const float*)d_in[0];
    const float* W1    = (const float*)d_in[1];
    const float* b1    = (const float*)d_in[2];
    const float* W2    = (const float*)d_in[3];
    const float* b2    = (const float*)d_in[4];
    const float* gamma = (const float*)d_in[5];
    const float* beta  = (const float*)d_in[6];
    float* out = (float*)d_out;

    __nv_bfloat16 *xh, *xl, *hh, *hl, *w1h, *w1l, *w2h, *w2l;
    float* obuf;
    cudaGetSymbolAddress((void**)&xh, g_xh);
    cudaGetSymbolAddress((void**)&xl, g_xl);
    cudaGetSymbolAddress((void**)&hh, g_hh);
    cudaGetSymbolAddress((void**)&hl, g_hl);
    cudaGetSymbolAddress((void**)&obuf, g_o);
    cudaGetSymbolAddress((void**)&w1h, g_w1h);
    cudaGetSymbolAddress((void**)&w1l, g_w1l);
    cudaGetSymbolAddress((void**)&w2h, g_w2h);
    cudaGetSymbolAddress((void**)&w2l, g_w2l);

    const int SMEM_GEMM = 55552;
    cudaFuncSetAttribute(gemm_ws_kernel<0>, cudaFuncAttributeMaxDynamicSharedMemorySize, SMEM_GEMM);
    cudaFuncSetAttribute(gemm_ws_kernel<1>, cudaFuncAttributeMaxDynamicSharedMemorySize, SMEM_GEMM);

    wsplit_kernel<<<(CDIM * PDIM * PDIM) / 256, 256>>>(W1, W2, w1h, w1l, w2h, w2l);
    xsplit_kernel<<<dim3(CDIM / 32, BDIM), 256>>>(x, xh, xl);
    gemm_ws_kernel<0><<<dim3(BDIM / 128, CDIM), 256, SMEM_GEMM>>>(xh, xl, w1h, w1l, b1, hh, hl, nullptr);
    gemm_ws_kernel<1><<<dim3(BDIM / 128, CDIM), 256, SMEM_GEMM>>>(hh, hl, w2h, w2l, b2, nullptr, nullptr, obuf);
    ln_kernel<<<dim3(PDIM / 16, BDIM), 256>>>(obuf, x, gamma, beta, out);
}

// round 5
// speedup vs baseline: 1.8195x; 1.1325x over previous
#include <cuda_runtime.h>
#include <cuda_bf16.h>
#include <math.h>
#include <stdint.h>

#define BDIM 1024
#define PDIM 64
#define CDIM 512

// ---------------------------------------------------------------------------
// Scratch (device globals; no allocations allowed)
// ---------------------------------------------------------------------------
__device__ __align__(128) __nv_bfloat16 g_xh[(size_t)CDIM * BDIM * PDIM];
__device__ __align__(128) __nv_bfloat16 g_xl[(size_t)CDIM * BDIM * PDIM];
__device__ __align__(128) float         g_o [(size_t)CDIM * BDIM * PDIM];
__device__ __align__(128) __nv_bfloat16 g_w1h[(size_t)CDIM * PDIM * PDIM];
__device__ __align__(128) __nv_bfloat16 g_w1l[(size_t)CDIM * PDIM * PDIM];
__device__ __align__(128) __nv_bfloat16 g_w2h[(size_t)CDIM * PDIM * PDIM];
__device__ __align__(128) __nv_bfloat16 g_w2l[(size_t)CDIM * PDIM * PDIM];

// ---------------------------------------------------------------------------
// mma.sync / ldmatrix helpers (baseline PTX — compiles for compute_103)
// ---------------------------------------------------------------------------
__device__ __forceinline__ uint32_t smem_u32(const void* p) {
    uint32_t a;
    asm("{ .reg .u64 t; cvta.to.shared.u64 t, %1; cvt.u32.u64 %0, t; }" : "=r"(a) : "l"(p));
    return a;
}

#define LDM_X4(r, addr)                                                         \
    asm volatile("ldmatrix.sync.aligned.m8n8.x4.shared.b16 {%0,%1,%2,%3}, [%4];"\
        : "=r"((r)[0]), "=r"((r)[1]), "=r"((r)[2]), "=r"((r)[3]) : "r"(addr))

// NON-trans x2: B smem rows are [n][k] with k contiguous -> fragment layout
// lane g*4+t = (n=g, k=2t,2t+1) exactly as mma row.col requires.
#define LDM_X2(r, addr)                                                         \
    asm volatile("ldmatrix.sync.aligned.m8n8.x2.shared.b16 {%0,%1}, [%2];"      \
        : "=r"((r)[0]), "=r"((r)[1]) : "r"(addr))

#define MMA_BF16(c, a, b)                                                       \
    asm volatile("mma.sync.aligned.m16n8k16.row.col.f32.bf16.bf16.f32 "         \
        "{%0,%1,%2,%3}, {%4,%5,%6,%7}, {%8,%9}, {%0,%1,%2,%3};"                 \
        : "+f"((c)[0]), "+f"((c)[1]), "+f"((c)[2]), "+f"((c)[3])                \
        : "r"((a)[0]), "r"((a)[1]), "r"((a)[2]), "r"((a)[3]),                   \
          "r"((b)[0]), "r"((b)[1]))

// ---------------------------------------------------------------------------
// Kernel 1: split W -> bf16 hi/lo (elementwise)
// ---------------------------------------------------------------------------
__global__ void __launch_bounds__(256)
wsplit_kernel(const float* __restrict__ W1, const float* __restrict__ W2,
              __nv_bfloat16* __restrict__ w1h, __nv_bfloat16* __restrict__ w1l,
              __nv_bfloat16* __restrict__ w2h, __nv_bfloat16* __restrict__ w2l)
{
    size_t i = (size_t)blockIdx.x * 256 + threadIdx.x;
    float a = W1[i];
    __nv_bfloat16 h = __float2bfloat16(a);
    w1h[i] = h;
    w1l[i] = __float2bfloat16(a - __bfloat162float(h));
    float b = W2[i];
    __nv_bfloat16 h2 = __float2bfloat16(b);
    w2h[i] = h2;
    w2l[i] = __float2bfloat16(b - __bfloat162float(h2));
}

// ---------------------------------------------------------------------------
// Kernel 2: transpose + split  x[b,p,c] -> xh/xl[c,b,p] (bf16)
// ---------------------------------------------------------------------------
__global__ void __launch_bounds__(256)
xsplit_kernel(const float* __restrict__ x,
              __nv_bfloat16* __restrict__ xh, __nv_bfloat16* __restrict__ xl)
{
    __shared__ float sm[32][65];
    const int b = blockIdx.y;
    const int c0 = blockIdx.x * 32;

    for (int i = threadIdx.x; i < 32 * 64; i += 256) {
        int p = i >> 5, cc = i & 31;
        sm[cc][p] = x[((size_t)b * PDIM + p) * CDIM + c0 + cc];
    }
    __syncthreads();

    const int cc = threadIdx.x >> 3;
    const int p0 = (threadIdx.x & 7) * 8;
    __nv_bfloat16 hv[8], lv[8];
#pragma unroll
    for (int i = 0; i < 8; i++) {
        float v = sm[cc][p0 + i];
        hv[i] = __float2bfloat16(v);
        lv[i] = __float2bfloat16(v - __bfloat162float(hv[i]));
    }
    size_t base = ((size_t)(c0 + cc) * BDIM + b) * PDIM + p0;
    *(uint4*)(xh + base) = *(uint4*)hv;
    *(uint4*)(xl + base) = *(uint4*)lv;
}

// ---------------------------------------------------------------------------
// Kernel 3: FUSED double GEMM per (c, 128-batch tile):
//   h = GELU(x W1^T + b1)   [split in smem, warp-private rows]
//   o = h W2^T + b2         -> g_o [c][b][q] fp32
// Split-3 bf16 per GEMM: D = Ah·Bh + Ah·Bl + Al·Bh.
// ---------------------------------------------------------------------------
__global__ void __launch_bounds__(256)
fused_gemm_kernel(const __nv_bfloat16* __restrict__ Ah_g, const __nv_bfloat16* __restrict__ Al_g,
                  const __nv_bfloat16* __restrict__ W1h_g, const __nv_bfloat16* __restrict__ W1l_g,
                  const __nv_bfloat16* __restrict__ W2h_g, const __nv_bfloat16* __restrict__ W2l_g,
                  const float* __restrict__ b1, const float* __restrict__ b2,
                  float* __restrict__ outF)
{
    extern __shared__ __align__(16) char smem[];
    // byte offsets (tile row stride 144 = 72 halves)
    const uint32_t AH = 0, AL = 18432;                // A tiles: 128 rows x 144B
    const uint32_t B1H = 36864, B1L = 46080;          // W1 tiles: 64 rows x 144B
    const uint32_t B2H = 55296, B2L = 64512;          // W2 tiles
    const uint32_t BIAS1 = 73728, BIAS2 = 73984;      // 64 floats each

    const int tid  = threadIdx.x;
    const int warp = tid >> 5;
    const int lane = tid & 31;
    const int b0   = blockIdx.x * 128;
    const int c    = blockIdx.y;

    // ---- stage tiles ----
    {
        const uint4* sAh = (const uint4*)(Ah_g + ((size_t)c * BDIM + b0) * PDIM);
        const uint4* sAl = (const uint4*)(Al_g + ((size_t)c * BDIM + b0) * PDIM);
        for (int i = tid; i < 1024; i += 256) {           // 128 rows x 8 chunks
            int row = i >> 3, ch = i & 7;
            *(uint4*)(smem + AH + row * 144 + ch * 16) = sAh[i];
            *(uint4*)(smem + AL + row * 144 + ch * 16) = sAl[i];
        }
        const uint4* s1h = (const uint4*)(W1h_g + (size_t)c * PDIM * PDIM);
        const uint4* s1l = (const uint4*)(W1l_g + (size_t)c * PDIM * PDIM);
        const uint4* s2h = (const uint4*)(W2h_g + (size_t)c * PDIM * PDIM);
        const uint4* s2l = (const uint4*)(W2l_g + (size_t)c * PDIM * PDIM);
        for (int i = tid; i < 512; i += 256) {            // 64 rows x 8 chunks
            int row = i >> 3, ch = i & 7;
            *(uint4*)(smem + B1H + row * 144 + ch * 16) = s1h[i];
            *(uint4*)(smem + B1L + row * 144 + ch * 16) = s1l[i];
            *(uint4*)(smem + B2H + row * 144 + ch * 16) = s2h[i];
            *(uint4*)(smem + B2L + row * 144 + ch * 16) = s2l[i];
        }
        if (tid < 64) {
            ((float*)(smem + BIAS1))[tid] = b1[(size_t)c * PDIM + tid];
            ((float*)(smem + BIAS2))[tid] = b2[(size_t)c * PDIM + tid];
        }
    }
    __syncthreads();

    const uint32_t sb = smem_u32(smem);
    // A ldmatrix x4 (warp-private rows warp*16..+15)
    const uint32_t aAdrH = sb + AH + (uint32_t)(warp * 16 + (lane & 15)) * 144 + (uint32_t)(lane >> 4) * 16;
    const uint32_t aAdrL = aAdrH + (AL - AH);
    // B ldmatrix x2 (non-trans): lanes 0-7 -> n rows @ k-byte 0, 8-15 -> @ k-byte 16
    const uint32_t bBase = sb + (uint32_t)(lane & 7) * 144 + (uint32_t)((lane >> 3) & 1) * 16;

    const int gid = lane >> 2, tq = lane & 3;
    const int r0 = warp * 16 + gid, r1 = r0 + 8;

    // ================= GEMM 1 =================
    float acc[8][4] = {};
#pragma unroll
    for (int kc = 0; kc < 4; kc++) {
        uint32_t ah[4], al[4];
        LDM_X4(ah, aAdrH + kc * 32);
        LDM_X4(al, aAdrL + kc * 32);
#pragma unroll
        for (int n = 0; n < 8; n++) {
            uint32_t bh[2], bl[2];
            LDM_X2(bh, bBase + B1H + n * 1152 + kc * 32);
            LDM_X2(bl, bBase + B1L + n * 1152 + kc * 32);
            MMA_BF16(acc[n], ah, bh);
            MMA_BF16(acc[n], ah, bl);
            MMA_BF16(acc[n], al, bh);
        }
    }

    // ---- epilogue 1: bias + exact GELU + bf16 split, written back into the
    //      warp-private A rows (h becomes the next A tile). ----
    {
        const float* bs = (const float*)(smem + BIAS1);
#pragma unroll
        for (int n = 0; n < 8; n++) {
            int q = n * 8 + 2 * tq;
            float v[4];
            v[0] = acc[n][0] + bs[q];
            v[1] = acc[n][1] + bs[q + 1];
            v[2] = acc[n][2] + bs[q];
            v[3] = acc[n][3] + bs[q + 1];
#pragma unroll
            for (int j = 0; j < 4; j++)
                v[j] = 0.5f * v[j] * (1.0f + erff(v[j] * 0.70710678118654752f));
            uint32_t hi[2], lo[2];
#pragma unroll
            for (int half = 0; half < 2; half++) {
                __nv_bfloat16 h0 = __float2bfloat16(v[2 * half]);
                __nv_bfloat16 h1 = __float2bfloat16(v[2 * half + 1]);
                __nv_bfloat16 l0 = __float2bfloat16(v[2 * half] - __bfloat162float(h0));
                __nv_bfloat16 l1 = __float2bfloat16(v[2 * half + 1] - __bfloat162float(h1));
                hi[half] = ((uint32_t)__bfloat16_as_ushort(h1) << 16) | __bfloat16_as_ushort(h0);
                lo[half] = ((uint32_t)__bfloat16_as_ushort(l1) << 16) | __bfloat16_as_ushort(l0);
            }
            int col = q * 2;  // byte offset of half q within 128B row payload
            *(uint32_t*)(smem + AH + r0 * 144 + col) = hi[0];
            *(uint32_t*)(smem + AL + r0 * 144 + col) = lo[0];
            *(uint32_t*)(smem + AH + r1 * 144 + col) = hi[1];
            *(uint32_t*)(smem + AL + r1 * 144 + col) = lo[1];
        }
    }
    __syncwarp();   // A rows are warp-private: warp-level ordering suffices

    // ================= GEMM 2 =================
    float acc2[8][4] = {};
#pragma unroll
    for (int kc = 0; kc < 4; kc++) {
        uint32_t ah[4], al[4];
        LDM_X4(ah, aAdrH + kc * 32);
        LDM_X4(al, aAdrL + kc * 32);
#pragma unroll
        for (int n = 0; n < 8; n++) {
            uint32_t bh[2], bl[2];
            LDM_X2(bh, bBase + B2H + n * 1152 + kc * 32);
            LDM_X2(bl, bBase + B2L + n * 1152 + kc * 32);
            MMA_BF16(acc2[n], ah, bh);
            MMA_BF16(acc2[n], ah, bl);
            MMA_BF16(acc2[n], al, bh);
        }
    }
    __syncthreads();   // done with all tiles; reuse smem for fp32 staging

    // ---- epilogue 2: bias2 -> coalesced fp32 store via smem (stride 272B) ----
    {
        const float* bs = (const float*)(smem + BIAS2);
#pragma unroll
        for (int n = 0; n < 8; n++) {
            int q = n * 8 + 2 * tq;
            float2 lo2, hi2;
            lo2.x = acc2[n][0] + bs[q];
            lo2.y = acc2[n][1] + bs[q + 1];
            hi2.x = acc2[n][2] + bs[q];
            hi2.y = acc2[n][3] + bs[q + 1];
            *(float2*)(smem + r0 * 272 + q * 4) = lo2;
            *(float2*)(smem + r1 * 272 + q * 4) = hi2;
        }
    }
    __syncthreads();
    {
        float* dF = outF + ((size_t)c * BDIM + b0) * PDIM;
        for (int i = tid; i < 2048; i += 256) {
            int row = i >> 4, ch = i & 15;
            *(uint4*)(dF + row * 64 + ch * 4) = *(uint4*)(smem + row * 272 + ch * 16);
        }
    }
}

// ---------------------------------------------------------------------------
// Kernel 4: residual + LayerNorm over channels.
//   out[b,q,c] = LN_c( o[c,b,q] + x[b,q,c] ) * gamma + beta
// ---------------------------------------------------------------------------
__global__ void __launch_bounds__(256)
ln_kernel(const float* __restrict__ o, const float* __restrict__ x,
          const float* __restrict__ gamma, const float* __restrict__ beta,
          float* __restrict__ out)
{
    __shared__ float res[16][517];
    __shared__ float psum[16][17], psqs[16][17];
    __shared__ float pmean[16], pinv[16];

    const int b = blockIdx.y;
    const int q0 = blockIdx.x * 16;
    const size_t xbase = ((size_t)b * PDIM + q0) * CDIM;

    for (int i = threadIdx.x; i < 16 * 512; i += 256) {
        int q = i >> 9, cc = i & 511;
        res[q][cc] = x[xbase + (size_t)q * CDIM + cc];
    }
    __syncthreads();

    {
        const int q = threadIdx.x & 15, cg = threadIdx.x >> 4;
        const size_t orow = (size_t)b * PDIM + q0 + q;
        float s = 0.f, ss = 0.f;
#pragma unroll 4
        for (int j = 0; j < 32; j++) {
            int cc = cg * 32 + j;
            float v = res[q][cc] + o[(size_t)cc * (BDIM * PDIM) + orow];
            res[q][cc] = v;
            s += v; ss += v * v;
        }
        psum[q][cg] = s; psqs[q][cg] = ss;
    }
    __syncthreads();

    if (threadIdx.x < 16) {
        float S = 0.f, SS = 0.f;
#pragma unroll
        for (int g = 0; g < 16; g++) { S += psum[threadIdx.x][g]; SS += psqs[threadIdx.x][g]; }
        float mean = S * (1.0f / 512.0f);
        float var  = SS * (1.0f / 512.0f) - mean * mean;
        pmean[threadIdx.x] = mean;
        pinv[threadIdx.x]  = rsqrtf(var + 1e-5f);
    }
    __syncthreads();

    for (int i = threadIdx.x; i < 16 * 512; i += 256) {
        int q = i >> 9, cc = i & 511;
        out[xbase + (size_t)q * CDIM + cc] =
            (res[q][cc] - pmean[q]) * pinv[q] * gamma[cc] + beta[cc];
    }
}

// ---------------------------------------------------------------------------
extern "C" void kernel_launch(void* const* d_in, const int* in_sizes, int n_in,
                              void* d_out, int out_size)
{
    const float* x     = (const float*)d_in[0];
    const float* W1    = (const float*)d_in[1];
    const float* b1    = (const float*)d_in[2];
    const float* W2    = (const float*)d_in[3];
    const float* b2    = (const float*)d_in[4];
    const float* gamma = (const float*)d_in[5];
    const float* beta  = (const float*)d_in[6];
    float* out = (float*)d_out;

    __nv_bfloat16 *xh, *xl, *w1h, *w1l, *w2h, *w2l;
    float* obuf;
    cudaGetSymbolAddress((void**)&xh, g_xh);
    cudaGetSymbolAddress((void**)&xl, g_xl);
    cudaGetSymbolAddress((void**)&obuf, g_o);
    cudaGetSymbolAddress((void**)&w1h, g_w1h);
    cudaGetSymbolAddress((void**)&w1l, g_w1l);
    cudaGetSymbolAddress((void**)&w2h, g_w2h);
    cudaGetSymbolAddress((void**)&w2l, g_w2l);

    const int SMEM_FUSED = 74240;
    cudaFuncSetAttribute(fused_gemm_kernel, cudaFuncAttributeMaxDynamicSharedMemorySize, SMEM_FUSED);

    wsplit_kernel<<<(CDIM * PDIM * PDIM) / 256, 256>>>(W1, W2, w1h, w1l, w2h, w2l);
    xsplit_kernel<<<dim3(CDIM / 32, BDIM), 256>>>(x, xh, xl);
    fused_gemm_kernel<<<dim3(BDIM / 128, CDIM), 256, SMEM_FUSED>>>(
        xh, xl, w1h, w1l, w2h, w2l, b1, b2, obuf);
    ln_kernel<<<dim3(PDIM / 16, BDIM), 256>>>(obuf, x, gamma, beta, out);
}

// round 6
// speedup vs baseline: 1.9442x; 1.0685x over previous
#include <cuda_runtime.h>
#include <cuda_bf16.h>
#include <math.h>
#include <stdint.h>

#define BDIM 1024
#define PDIM 64
#define CDIM 512

// ---------------------------------------------------------------------------
// Scratch (device globals; no allocations allowed)
// ---------------------------------------------------------------------------
__device__ __align__(128) __nv_bfloat16 g_xh[(size_t)CDIM * BDIM * PDIM];
__device__ __align__(128) __nv_bfloat16 g_xl[(size_t)CDIM * BDIM * PDIM];
__device__ __align__(128) float         g_res[(size_t)CDIM * BDIM * PDIM];
__device__ __align__(128) __nv_bfloat16 g_w1h[(size_t)CDIM * PDIM * PDIM];
__device__ __align__(128) __nv_bfloat16 g_w1l[(size_t)CDIM * PDIM * PDIM];
__device__ __align__(128) __nv_bfloat16 g_w2h[(size_t)CDIM * PDIM * PDIM];
__device__ __align__(128) __nv_bfloat16 g_w2l[(size_t)CDIM * PDIM * PDIM];

// ---------------------------------------------------------------------------
// mma.sync / ldmatrix helpers (baseline PTX — compiles for compute_103)
// ---------------------------------------------------------------------------
__device__ __forceinline__ uint32_t smem_u32(const void* p) {
    uint32_t a;
    asm("{ .reg .u64 t; cvta.to.shared.u64 t, %1; cvt.u32.u64 %0, t; }" : "=r"(a) : "l"(p));
    return a;
}

#define LDM_X4(r, addr)                                                         \
    asm volatile("ldmatrix.sync.aligned.m8n8.x4.shared.b16 {%0,%1,%2,%3}, [%4];"\
        : "=r"((r)[0]), "=r"((r)[1]), "=r"((r)[2]), "=r"((r)[3]) : "r"(addr))

#define LDM_X2(r, addr)                                                         \
    asm volatile("ldmatrix.sync.aligned.m8n8.x2.shared.b16 {%0,%1}, [%2];"      \
        : "=r"((r)[0]), "=r"((r)[1]) : "r"(addr))

#define MMA_BF16(c, a, b)                                                       \
    asm volatile("mma.sync.aligned.m16n8k16.row.col.f32.bf16.bf16.f32 "         \
        "{%0,%1,%2,%3}, {%4,%5,%6,%7}, {%8,%9}, {%0,%1,%2,%3};"                 \
        : "+f"((c)[0]), "+f"((c)[1]), "+f"((c)[2]), "+f"((c)[3])                \
        : "r"((a)[0]), "r"((a)[1]), "r"((a)[2]), "r"((a)[3]),                   \
          "r"((b)[0]), "r"((b)[1]))

// ---------------------------------------------------------------------------
// Kernel 1: split W -> bf16 hi/lo (elementwise)
// ---------------------------------------------------------------------------
__global__ void __launch_bounds__(256)
wsplit_kernel(const float* __restrict__ W1, const float* __restrict__ W2,
              __nv_bfloat16* __restrict__ w1h, __nv_bfloat16* __restrict__ w1l,
              __nv_bfloat16* __restrict__ w2h, __nv_bfloat16* __restrict__ w2l)
{
    size_t i = (size_t)blockIdx.x * 256 + threadIdx.x;
    float a = W1[i];
    __nv_bfloat16 h = __float2bfloat16(a);
    w1h[i] = h;
    w1l[i] = __float2bfloat16(a - __bfloat162float(h));
    float b = W2[i];
    __nv_bfloat16 h2 = __float2bfloat16(b);
    w2h[i] = h2;
    w2l[i] = __float2bfloat16(b - __bfloat162float(h2));
}

// ---------------------------------------------------------------------------
// Kernel 2: transpose + split  x[b,p,c] -> xh/xl[c,b,p] (bf16)
// ---------------------------------------------------------------------------
__global__ void __launch_bounds__(256)
xsplit_kernel(const float* __restrict__ x,
              __nv_bfloat16* __restrict__ xh, __nv_bfloat16* __restrict__ xl)
{
    __shared__ float sm[32][65];
    const int b = blockIdx.y;
    const int c0 = blockIdx.x * 32;

    for (int i = threadIdx.x; i < 32 * 64; i += 256) {
        int p = i >> 5, cc = i & 31;
        sm[cc][p] = x[((size_t)b * PDIM + p) * CDIM + c0 + cc];
    }
    __syncthreads();

    const int cc = threadIdx.x >> 3;
    const int p0 = (threadIdx.x & 7) * 8;
    __nv_bfloat16 hv[8], lv[8];
#pragma unroll
    for (int i = 0; i < 8; i++) {
        float v = sm[cc][p0 + i];
        hv[i] = __float2bfloat16(v);
        lv[i] = __float2bfloat16(v - __bfloat162float(hv[i]));
    }
    size_t base = ((size_t)(c0 + cc) * BDIM + b) * PDIM + p0;
    *(uint4*)(xh + base) = *(uint4*)hv;
    *(uint4*)(xl + base) = *(uint4*)lv;
}

// ---------------------------------------------------------------------------
// Kernel 3: FUSED double GEMM per (c, 128-batch tile):
//   h   = GELU(x W1^T + b1)      [split in smem, warp-private rows]
//   res = h W2^T + b2 + x        -> g_res [c][b][q] fp32  (residual fused)
// Split-3 bf16 per GEMM: D = Ah·Bh + Ah·Bl + Al·Bh.
// ---------------------------------------------------------------------------
__global__ void __launch_bounds__(256)
fused_gemm_kernel(const __nv_bfloat16* __restrict__ Ah_g, const __nv_bfloat16* __restrict__ Al_g,
                  const __nv_bfloat16* __restrict__ W1h_g, const __nv_bfloat16* __restrict__ W1l_g,
                  const __nv_bfloat16* __restrict__ W2h_g, const __nv_bfloat16* __restrict__ W2l_g,
                  const float* __restrict__ b1, const float* __restrict__ b2,
                  float* __restrict__ outF)
{
    extern __shared__ __align__(16) char smem[];
    const uint32_t AH = 0, AL = 18432;                // A tiles: 128 rows x 144B
    const uint32_t B1H = 36864, B1L = 46080;          // W1 tiles: 64 rows x 144B
    const uint32_t B2H = 55296, B2L = 64512;          // W2 tiles
    const uint32_t BIAS1 = 73728, BIAS2 = 73984;

    const int tid  = threadIdx.x;
    const int warp = tid >> 5;
    const int lane = tid & 31;
    const int b0   = blockIdx.x * 128;
    const int c    = blockIdx.y;

    // ---- stage tiles ----
    {
        const uint4* sAh = (const uint4*)(Ah_g + ((size_t)c * BDIM + b0) * PDIM);
        const uint4* sAl = (const uint4*)(Al_g + ((size_t)c * BDIM + b0) * PDIM);
        for (int i = tid; i < 1024; i += 256) {
            int row = i >> 3, ch = i & 7;
            *(uint4*)(smem + AH + row * 144 + ch * 16) = sAh[i];
            *(uint4*)(smem + AL + row * 144 + ch * 16) = sAl[i];
        }
        const uint4* s1h = (const uint4*)(W1h_g + (size_t)c * PDIM * PDIM);
        const uint4* s1l = (const uint4*)(W1l_g + (size_t)c * PDIM * PDIM);
        const uint4* s2h = (const uint4*)(W2h_g + (size_t)c * PDIM * PDIM);
        const uint4* s2l = (const uint4*)(W2l_g + (size_t)c * PDIM * PDIM);
        for (int i = tid; i < 512; i += 256) {
            int row = i >> 3, ch = i & 7;
            *(uint4*)(smem + B1H + row * 144 + ch * 16) = s1h[i];
            *(uint4*)(smem + B1L + row * 144 + ch * 16) = s1l[i];
            *(uint4*)(smem + B2H + row * 144 + ch * 16) = s2h[i];
            *(uint4*)(smem + B2L + row * 144 + ch * 16) = s2l[i];
        }
        if (tid < 64) {
            ((float*)(smem + BIAS1))[tid] = b1[(size_t)c * PDIM + tid];
            ((float*)(smem + BIAS2))[tid] = b2[(size_t)c * PDIM + tid];
        }
    }
    __syncthreads();

    const uint32_t sb = smem_u32(smem);
    const uint32_t aAdrH = sb + AH + (uint32_t)(warp * 16 + (lane & 15)) * 144 + (uint32_t)(lane >> 4) * 16;
    const uint32_t aAdrL = aAdrH + (AL - AH);
    const uint32_t bBase = sb + (uint32_t)(lane & 7) * 144 + (uint32_t)((lane >> 3) & 1) * 16;

    const int gid = lane >> 2, tq = lane & 3;
    const int r0 = warp * 16 + gid, r1 = r0 + 8;

    // ================= GEMM 1 =================
    float acc[8][4] = {};
#pragma unroll
    for (int kc = 0; kc < 4; kc++) {
        uint32_t ah[4], al[4];
        LDM_X4(ah, aAdrH + kc * 32);
        LDM_X4(al, aAdrL + kc * 32);
#pragma unroll
        for (int n = 0; n < 8; n++) {
            uint32_t bh[2], bl[2];
            LDM_X2(bh, bBase + B1H + n * 1152 + kc * 32);
            LDM_X2(bl, bBase + B1L + n * 1152 + kc * 32);
            MMA_BF16(acc[n], ah, bh);
            MMA_BF16(acc[n], ah, bl);
            MMA_BF16(acc[n], al, bh);
        }
    }

    // ---- epilogue 1: bias + exact GELU + bf16 split back into A rows ----
    {
        const float* bs = (const float*)(smem + BIAS1);
#pragma unroll
        for (int n = 0; n < 8; n++) {
            int q = n * 8 + 2 * tq;
            float v[4];
            v[0] = acc[n][0] + bs[q];
            v[1] = acc[n][1] + bs[q + 1];
            v[2] = acc[n][2] + bs[q];
            v[3] = acc[n][3] + bs[q + 1];
#pragma unroll
            for (int j = 0; j < 4; j++)
                v[j] = 0.5f * v[j] * (1.0f + erff(v[j] * 0.70710678118654752f));
            uint32_t hi[2], lo[2];
#pragma unroll
            for (int half = 0; half < 2; half++) {
                __nv_bfloat16 h0 = __float2bfloat16(v[2 * half]);
                __nv_bfloat16 h1 = __float2bfloat16(v[2 * half + 1]);
                __nv_bfloat16 l0 = __float2bfloat16(v[2 * half] - __bfloat162float(h0));
                __nv_bfloat16 l1 = __float2bfloat16(v[2 * half + 1] - __bfloat162float(h1));
                hi[half] = ((uint32_t)__bfloat16_as_ushort(h1) << 16) | __bfloat16_as_ushort(h0);
                lo[half] = ((uint32_t)__bfloat16_as_ushort(l1) << 16) | __bfloat16_as_ushort(l0);
            }
            int col = q * 2;
            *(uint32_t*)(smem + AH + r0 * 144 + col) = hi[0];
            *(uint32_t*)(smem + AL + r0 * 144 + col) = lo[0];
            *(uint32_t*)(smem + AH + r1 * 144 + col) = hi[1];
            *(uint32_t*)(smem + AL + r1 * 144 + col) = lo[1];
        }
    }
    __syncwarp();   // A rows are warp-private

    // ================= GEMM 2 =================
    float acc2[8][4] = {};
#pragma unroll
    for (int kc = 0; kc < 4; kc++) {
        uint32_t ah[4], al[4];
        LDM_X4(ah, aAdrH + kc * 32);
        LDM_X4(al, aAdrL + kc * 32);
#pragma unroll
        for (int n = 0; n < 8; n++) {
            uint32_t bh[2], bl[2];
            LDM_X2(bh, bBase + B2H + n * 1152 + kc * 32);
            LDM_X2(bl, bBase + B2L + n * 1152 + kc * 32);
            MMA_BF16(acc2[n], ah, bh);
            MMA_BF16(acc2[n], ah, bl);
            MMA_BF16(acc2[n], al, bh);
        }
    }
    __syncthreads();   // done with all tiles; reuse smem for fp32 staging

    // ---- epilogue 2: +bias2, stage fp32, then add residual x and store ----
    {
        const float* bs = (const float*)(smem + BIAS2);
#pragma unroll
        for (int n = 0; n < 8; n++) {
            int q = n * 8 + 2 * tq;
            float2 lo2, hi2;
            lo2.x = acc2[n][0] + bs[q];
            lo2.y = acc2[n][1] + bs[q + 1];
            hi2.x = acc2[n][2] + bs[q];
            hi2.y = acc2[n][3] + bs[q + 1];
            *(float2*)(smem + r0 * 272 + q * 4) = lo2;
            *(float2*)(smem + r1 * 272 + q * 4) = hi2;
        }
    }
    __syncthreads();
    {
        float* dF = outF + ((size_t)c * BDIM + b0) * PDIM;
        const __nv_bfloat16* xht = Ah_g + ((size_t)c * BDIM + b0) * PDIM;  // L1-hot
        const __nv_bfloat16* xlt = Al_g + ((size_t)c * BDIM + b0) * PDIM;
        for (int i = tid; i < 2048; i += 256) {
            int row = i >> 4, ch = i & 15;
            float4 v = *(float4*)(smem + row * 272 + ch * 16);
            uint2 xhp = *(const uint2*)(xht + row * 64 + ch * 4);
            uint2 xlp = *(const uint2*)(xlt + row * 64 + ch * 4);
            v.x += __uint_as_float(xhp.x << 16)        + __uint_as_float(xlp.x << 16);
            v.y += __uint_as_float(xhp.x & 0xFFFF0000u) + __uint_as_float(xlp.x & 0xFFFF0000u);
            v.z += __uint_as_float(xhp.y << 16)        + __uint_as_float(xlp.y << 16);
            v.w += __uint_as_float(xhp.y & 0xFFFF0000u) + __uint_as_float(xlp.y & 0xFFFF0000u);
            *(float4*)(dF + row * 64 + ch * 4) = v;
        }
    }
}

// ---------------------------------------------------------------------------
// Kernel 4: LayerNorm over channels (residual already folded into res).
//   out[b,q,c] = (res[c,b,q] - mean) * rsqrt(var+eps) * gamma[c] + beta[c]
// CTA = 16 (b,q) rows x 512 c. Thread = 4 consecutive rows (float4 gmem loads).
// ---------------------------------------------------------------------------
#define LNPAD 524
__global__ void __launch_bounds__(256)
ln_kernel(const float* __restrict__ res,
          const float* __restrict__ gamma, const float* __restrict__ beta,
          float* __restrict__ out)
{
    __shared__ float sres[16][LNPAD];
    __shared__ float psum[16][65], psqs[16][65];
    __shared__ float pmean[16], pinv[16];

    const int b  = blockIdx.y;
    const int q0 = blockIdx.x * 16;
    const int orow0 = b * PDIM + q0;

    const int rg = threadIdx.x & 3;    // row group: rows rg*4 .. rg*4+3
    const int cg = threadIdx.x >> 2;   // 0..63

    float s0 = 0.f, s1 = 0.f, s2 = 0.f, s3 = 0.f;
    float t0 = 0.f, t1 = 0.f, t2 = 0.f, t3 = 0.f;
#pragma unroll
    for (int it = 0; it < 8; it++) {
        int cc = cg + it * 64;
        float4 v = *(const float4*)(res + (size_t)cc * (BDIM * PDIM) + orow0 + rg * 4);
        sres[rg * 4 + 0][cc] = v.x;  s0 += v.x;  t0 += v.x * v.x;
        sres[rg * 4 + 1][cc] = v.y;  s1 += v.y;  t1 += v.y * v.y;
        sres[rg * 4 + 2][cc] = v.z;  s2 += v.z;  t2 += v.z * v.z;
        sres[rg * 4 + 3][cc] = v.w;  s3 += v.w;  t3 += v.w * v.w;
    }
    psum[rg * 4 + 0][cg] = s0;  psqs[rg * 4 + 0][cg] = t0;
    psum[rg * 4 + 1][cg] = s1;  psqs[rg * 4 + 1][cg] = t1;
    psum[rg * 4 + 2][cg] = s2;  psqs[rg * 4 + 2][cg] = t2;
    psum[rg * 4 + 3][cg] = s3;  psqs[rg * 4 + 3][cg] = t3;
    __syncthreads();

    if (threadIdx.x < 16) {
        float S = 0.f, SS = 0.f;
#pragma unroll
        for (int g = 0; g < 64; g++) { S += psum[threadIdx.x][g]; SS += psqs[threadIdx.x][g]; }
        float mean = S * (1.0f / 512.0f);
        float var  = SS * (1.0f / 512.0f) - mean * mean;
        pmean[threadIdx.x] = mean;
        pinv[threadIdx.x]  = rsqrtf(var + 1e-5f);
    }
    __syncthreads();

    const size_t obase = (size_t)orow0 * CDIM;
    for (int i = threadIdx.x; i < 16 * 128; i += 256) {
        int q = i >> 7, cw = i & 127;
        float4 v = *(const float4*)(&sres[q][cw * 4]);
        float4 g = *(const float4*)(gamma + cw * 4);
        float4 bt = *(const float4*)(beta + cw * 4);
        float m = pmean[q], inv = pinv[q];
        float4 o4;
        o4.x = (v.x - m) * inv * g.x + bt.x;
        o4.y = (v.y - m) * inv * g.y + bt.y;
        o4.z = (v.z - m) * inv * g.z + bt.z;
        o4.w = (v.w - m) * inv * g.w + bt.w;
        *(float4*)(out + obase + (size_t)q * CDIM + cw * 4) = o4;
    }
}

// ---------------------------------------------------------------------------
extern "C" void kernel_launch(void* const* d_in, const int* in_sizes, int n_in,
                              void* d_out, int out_size)
{
    const float* x     = (const float*)d_in[0];
    const float* W1    = (const float*)d_in[1];
    const float* b1    = (const float*)d_in[2];
    const float* W2    = (const float*)d_in[3];
    const float* b2    = (const float*)d_in[4];
    const float* gamma = (const float*)d_in[5];
    const float* beta  = (const float*)d_in[6];
    float* out = (float*)d_out;

    __nv_bfloat16 *xh, *xl, *w1h, *w1l, *w2h, *w2l;
    float* resbuf;
    cudaGetSymbolAddress((void**)&xh, g_xh);
    cudaGetSymbolAddress((void**)&xl, g_xl);
    cudaGetSymbolAddress((void**)&resbuf, g_res);
    cudaGetSymbolAddress((void**)&w1h, g_w1h);
    cudaGetSymbolAddress((void**)&w1l, g_w1l);
    cudaGetSymbolAddress((void**)&w2h, g_w2h);
    cudaGetSymbolAddress((void**)&w2l, g_w2l);

    const int SMEM_FUSED = 74240;
    cudaFuncSetAttribute(fused_gemm_kernel, cudaFuncAttributeMaxDynamicSharedMemorySize, SMEM_FUSED);

    wsplit_kernel<<<(CDIM * PDIM * PDIM) / 256, 256>>>(W1, W2, w1h, w1l, w2h, w2l);
    xsplit_kernel<<<dim3(CDIM / 32, BDIM), 256>>>(x, xh, xl);
    fused_gemm_kernel<<<dim3(BDIM / 128, CDIM), 256, SMEM_FUSED>>>(
        xh, xl, w1h, w1l, w2h, w2l, b1, b2, resbuf);
    ln_kernel<<<dim3(PDIM / 16, BDIM), 256>>>(resbuf, gamma, beta, out);
}

// round 7
// speedup vs baseline: 2.2310x; 1.1475x over previous
#include <cuda_runtime.h>
#include <cuda_bf16.h>
#include <math.h>
#include <stdint.h>

#define BDIM 1024
#define PDIM 64
#define CDIM 512

// ---------------------------------------------------------------------------
// Scratch (device globals; no allocations allowed)
// ---------------------------------------------------------------------------
__device__ __align__(128) __nv_bfloat16 g_xh[(size_t)CDIM * BDIM * PDIM];
__device__ __align__(128) __nv_bfloat16 g_xl[(size_t)CDIM * BDIM * PDIM];
__device__ __align__(128) float         g_res[(size_t)CDIM * BDIM * PDIM];
__device__ __align__(128) __nv_bfloat16 g_w1h[(size_t)CDIM * PDIM * PDIM];
__device__ __align__(128) __nv_bfloat16 g_w1l[(size_t)CDIM * PDIM * PDIM];
__device__ __align__(128) __nv_bfloat16 g_w2h[(size_t)CDIM * PDIM * PDIM];
__device__ __align__(128) __nv_bfloat16 g_w2l[(size_t)CDIM * PDIM * PDIM];

// ---------------------------------------------------------------------------
// mma.sync / ldmatrix helpers (baseline PTX — compiles for compute_103)
// ---------------------------------------------------------------------------
__device__ __forceinline__ uint32_t smem_u32(const void* p) {
    uint32_t a;
    asm("{ .reg .u64 t; cvta.to.shared.u64 t, %1; cvt.u32.u64 %0, t; }" : "=r"(a) : "l"(p));
    return a;
}

#define LDM_X4(r, addr)                                                         \
    asm volatile("ldmatrix.sync.aligned.m8n8.x4.shared.b16 {%0,%1,%2,%3}, [%4];"\
        : "=r"((r)[0]), "=r"((r)[1]), "=r"((r)[2]), "=r"((r)[3]) : "r"(addr))

#define LDM_X2(r, addr)                                                         \
    asm volatile("ldmatrix.sync.aligned.m8n8.x2.shared.b16 {%0,%1}, [%2];"      \
        : "=r"((r)[0]), "=r"((r)[1]) : "r"(addr))

#define MMA_BF16(c, a, b)                                                       \
    asm volatile("mma.sync.aligned.m16n8k16.row.col.f32.bf16.bf16.f32 "         \
        "{%0,%1,%2,%3}, {%4,%5,%6,%7}, {%8,%9}, {%0,%1,%2,%3};"                 \
        : "+f"((c)[0]), "+f"((c)[1]), "+f"((c)[2]), "+f"((c)[3])                \
        : "r"((a)[0]), "r"((a)[1]), "r"((a)[2]), "r"((a)[3]),                   \
          "r"((b)[0]), "r"((b)[1]))

// ---------------------------------------------------------------------------
// Kernel 1: split W -> bf16 hi/lo, 8 elements per thread (vectorized)
// ---------------------------------------------------------------------------
__global__ void __launch_bounds__(256)
wsplit_kernel(const float* __restrict__ W1, const float* __restrict__ W2,
              __nv_bfloat16* __restrict__ w1h, __nv_bfloat16* __restrict__ w1l,
              __nv_bfloat16* __restrict__ w2h, __nv_bfloat16* __restrict__ w2l)
{
    size_t i8 = ((size_t)blockIdx.x * 256 + threadIdx.x) * 8;
#pragma unroll
    for (int w = 0; w < 2; w++) {
        const float* src = w ? W2 : W1;
        __nv_bfloat16* dh = w ? w2h : w1h;
        __nv_bfloat16* dl = w ? w2l : w1l;
        float v[8];
        *(float4*)(v)     = *(const float4*)(src + i8);
        *(float4*)(v + 4) = *(const float4*)(src + i8 + 4);
        __nv_bfloat16 hv[8], lv[8];
#pragma unroll
        for (int j = 0; j < 8; j++) {
            hv[j] = __float2bfloat16(v[j]);
            lv[j] = __float2bfloat16(v[j] - __bfloat162float(hv[j]));
        }
        *(uint4*)(dh + i8) = *(uint4*)hv;
        *(uint4*)(dl + i8) = *(uint4*)lv;
    }
}

// ---------------------------------------------------------------------------
// Kernel 2: transpose + split  x[b,p,c] -> xh/xl[c,b,p] (bf16).
// CTA = 4 batches x 32 channels (amortized; conflict-free stride-261 smem).
// ---------------------------------------------------------------------------
__global__ void __launch_bounds__(256)
xsplit_kernel(const float* __restrict__ x,
              __nv_bfloat16* __restrict__ xh, __nv_bfloat16* __restrict__ xl)
{
    __shared__ float sm[32][261];   // [cc][b*64+p], stride 261 (5 mod 32, odd)
    const int b0 = blockIdx.y * 4;
    const int c0 = blockIdx.x * 32;

    for (int i = threadIdx.x; i < 4 * 64 * 32; i += 256) {
        int cc = i & 31, p = (i >> 5) & 63, b = i >> 11;
        sm[cc][b * 64 + p] = x[((size_t)(b0 + b) * PDIM + p) * CDIM + c0 + cc];
    }
    __syncthreads();

    const int cc = threadIdx.x >> 3;
    const int p0 = (threadIdx.x & 7) * 8;
#pragma unroll
    for (int b = 0; b < 4; b++) {
        __nv_bfloat16 hv[8], lv[8];
#pragma unroll
        for (int i = 0; i < 8; i++) {
            float v = sm[cc][b * 64 + p0 + i];
            hv[i] = __float2bfloat16(v);
            lv[i] = __float2bfloat16(v - __bfloat162float(hv[i]));
        }
        size_t base = ((size_t)(c0 + cc) * BDIM + b0 + b) * PDIM + p0;
        *(uint4*)(xh + base) = *(uint4*)hv;
        *(uint4*)(xl + base) = *(uint4*)lv;
    }
}

// ---------------------------------------------------------------------------
// Kernel 3: FUSED double GEMM per (c, 128-batch tile) [unchanged from R6]
// ---------------------------------------------------------------------------
__global__ void __launch_bounds__(256)
fused_gemm_kernel(const __nv_bfloat16* __restrict__ Ah_g, const __nv_bfloat16* __restrict__ Al_g,
                  const __nv_bfloat16* __restrict__ W1h_g, const __nv_bfloat16* __restrict__ W1l_g,
                  const __nv_bfloat16* __restrict__ W2h_g, const __nv_bfloat16* __restrict__ W2l_g,
                  const float* __restrict__ b1, const float* __restrict__ b2,
                  float* __restrict__ outF)
{
    extern __shared__ __align__(16) char smem[];
    const uint32_t AH = 0, AL = 18432;
    const uint32_t B1H = 36864, B1L = 46080;
    const uint32_t B2H = 55296, B2L = 64512;
    const uint32_t BIAS1 = 73728, BIAS2 = 73984;

    const int tid  = threadIdx.x;
    const int warp = tid >> 5;
    const int lane = tid & 31;
    const int b0   = blockIdx.x * 128;
    const int c    = blockIdx.y;

    {
        const uint4* sAh = (const uint4*)(Ah_g + ((size_t)c * BDIM + b0) * PDIM);
        const uint4* sAl = (const uint4*)(Al_g + ((size_t)c * BDIM + b0) * PDIM);
        for (int i = tid; i < 1024; i += 256) {
            int row = i >> 3, ch = i & 7;
            *(uint4*)(smem + AH + row * 144 + ch * 16) = sAh[i];
            *(uint4*)(smem + AL + row * 144 + ch * 16) = sAl[i];
        }
        const uint4* s1h = (const uint4*)(W1h_g + (size_t)c * PDIM * PDIM);
        const uint4* s1l = (const uint4*)(W1l_g + (size_t)c * PDIM * PDIM);
        const uint4* s2h = (const uint4*)(W2h_g + (size_t)c * PDIM * PDIM);
        const uint4* s2l = (const uint4*)(W2l_g + (size_t)c * PDIM * PDIM);
        for (int i = tid; i < 512; i += 256) {
            int row = i >> 3, ch = i & 7;
            *(uint4*)(smem + B1H + row * 144 + ch * 16) = s1h[i];
            *(uint4*)(smem + B1L + row * 144 + ch * 16) = s1l[i];
            *(uint4*)(smem + B2H + row * 144 + ch * 16) = s2h[i];
            *(uint4*)(smem + B2L + row * 144 + ch * 16) = s2l[i];
        }
        if (tid < 64) {
            ((float*)(smem + BIAS1))[tid] = b1[(size_t)c * PDIM + tid];
            ((float*)(smem + BIAS2))[tid] = b2[(size_t)c * PDIM + tid];
        }
    }
    __syncthreads();

    const uint32_t sb = smem_u32(smem);
    const uint32_t aAdrH = sb + AH + (uint32_t)(warp * 16 + (lane & 15)) * 144 + (uint32_t)(lane >> 4) * 16;
    const uint32_t aAdrL = aAdrH + (AL - AH);
    const uint32_t bBase = sb + (uint32_t)(lane & 7) * 144 + (uint32_t)((lane >> 3) & 1) * 16;

    const int gid = lane >> 2, tq = lane & 3;
    const int r0 = warp * 16 + gid, r1 = r0 + 8;

    // ================= GEMM 1 =================
    float acc[8][4] = {};
#pragma unroll
    for (int kc = 0; kc < 4; kc++) {
        uint32_t ah[4], al[4];
        LDM_X4(ah, aAdrH + kc * 32);
        LDM_X4(al, aAdrL + kc * 32);
#pragma unroll
        for (int n = 0; n < 8; n++) {
            uint32_t bh[2], bl[2];
            LDM_X2(bh, bBase + B1H + n * 1152 + kc * 32);
            LDM_X2(bl, bBase + B1L + n * 1152 + kc * 32);
            MMA_BF16(acc[n], ah, bh);
            MMA_BF16(acc[n], ah, bl);
            MMA_BF16(acc[n], al, bh);
        }
    }

    {
        const float* bs = (const float*)(smem + BIAS1);
#pragma unroll
        for (int n = 0; n < 8; n++) {
            int q = n * 8 + 2 * tq;
            float v[4];
            v[0] = acc[n][0] + bs[q];
            v[1] = acc[n][1] + bs[q + 1];
            v[2] = acc[n][2] + bs[q];
            v[3] = acc[n][3] + bs[q + 1];
#pragma unroll
            for (int j = 0; j < 4; j++)
                v[j] = 0.5f * v[j] * (1.0f + erff(v[j] * 0.70710678118654752f));
            uint32_t hi[2], lo[2];
#pragma unroll
            for (int half = 0; half < 2; half++) {
                __nv_bfloat16 h0 = __float2bfloat16(v[2 * half]);
                __nv_bfloat16 h1 = __float2bfloat16(v[2 * half + 1]);
                __nv_bfloat16 l0 = __float2bfloat16(v[2 * half] - __bfloat162float(h0));
                __nv_bfloat16 l1 = __float2bfloat16(v[2 * half + 1] - __bfloat162float(h1));
                hi[half] = ((uint32_t)__bfloat16_as_ushort(h1) << 16) | __bfloat16_as_ushort(h0);
                lo[half] = ((uint32_t)__bfloat16_as_ushort(l1) << 16) | __bfloat16_as_ushort(l0);
            }
            int col = q * 2;
            *(uint32_t*)(smem + AH + r0 * 144 + col) = hi[0];
            *(uint32_t*)(smem + AL + r0 * 144 + col) = lo[0];
            *(uint32_t*)(smem + AH + r1 * 144 + col) = hi[1];
            *(uint32_t*)(smem + AL + r1 * 144 + col) = lo[1];
        }
    }
    __syncwarp();

    // ================= GEMM 2 =================
    float acc2[8][4] = {};
#pragma unroll
    for (int kc = 0; kc < 4; kc++) {
        uint32_t ah[4], al[4];
        LDM_X4(ah, aAdrH + kc * 32);
        LDM_X4(al, aAdrL + kc * 32);
#pragma unroll
        for (int n = 0; n < 8; n++) {
            uint32_t bh[2], bl[2];
            LDM_X2(bh, bBase + B2H + n * 1152 + kc * 32);
            LDM_X2(bl, bBase + B2L + n * 1152 + kc * 32);
            MMA_BF16(acc2[n], ah, bh);
            MMA_BF16(acc2[n], ah, bl);
            MMA_BF16(acc2[n], al, bh);
        }
    }
    __syncthreads();

    {
        const float* bs = (const float*)(smem + BIAS2);
#pragma unroll
        for (int n = 0; n < 8; n++) {
            int q = n * 8 + 2 * tq;
            float2 lo2, hi2;
            lo2.x = acc2[n][0] + bs[q];
            lo2.y = acc2[n][1] + bs[q + 1];
            hi2.x = acc2[n][2] + bs[q];
            hi2.y = acc2[n][3] + bs[q + 1];
            *(float2*)(smem + r0 * 272 + q * 4) = lo2;
            *(float2*)(smem + r1 * 272 + q * 4) = hi2;
        }
    }
    __syncthreads();
    {
        float* dF = outF + ((size_t)c * BDIM + b0) * PDIM;
        const __nv_bfloat16* xht = Ah_g + ((size_t)c * BDIM + b0) * PDIM;  // L1-hot
        const __nv_bfloat16* xlt = Al_g + ((size_t)c * BDIM + b0) * PDIM;
        for (int i = tid; i < 2048; i += 256) {
            int row = i >> 4, ch = i & 15;
            float4 v = *(float4*)(smem + row * 272 + ch * 16);
            uint2 xhp = *(const uint2*)(xht + row * 64 + ch * 4);
            uint2 xlp = *(const uint2*)(xlt + row * 64 + ch * 4);
            v.x += __uint_as_float(xhp.x << 16)        + __uint_as_float(xlp.x << 16);
            v.y += __uint_as_float(xhp.x & 0xFFFF0000u) + __uint_as_float(xlp.x & 0xFFFF0000u);
            v.z += __uint_as_float(xhp.y << 16)        + __uint_as_float(xlp.y << 16);
            v.w += __uint_as_float(xhp.y & 0xFFFF0000u) + __uint_as_float(xlp.y & 0xFFFF0000u);
            *(float4*)(dF + row * 64 + ch * 4) = v;
        }
    }
}

// ---------------------------------------------------------------------------
// Kernel 4: LayerNorm over channels, 32 (b,q) rows per CTA (full-line reads).
//   out[b,q,c] = (res[c,b,q] - mean) * rsqrt(var+eps) * gamma[c] + beta[c]
// ---------------------------------------------------------------------------
#define LNROWS 32
#define LNPAD  524   // floats per row (16B-aligned: 524*4 = 131*16)
__global__ void __launch_bounds__(256)
ln_kernel(const float* __restrict__ res,
          const float* __restrict__ gamma, const float* __restrict__ beta,
          float* __restrict__ out)
{
    extern __shared__ float sres[];            // [LNROWS][LNPAD] dynamic
    __shared__ float psum[LNROWS][33], psqs[LNROWS][33];
    __shared__ float pmean[LNROWS], pinv[LNROWS];

    const int b  = blockIdx.y;
    const int q0 = blockIdx.x * LNROWS;
    const int orow0 = b * PDIM + q0;

    // rg in 0..7 (bit2 = tid bit7), cg in 0..31
    const int rg = (threadIdx.x & 3) | ((threadIdx.x >> 7) << 2);
    const int cg = (threadIdx.x >> 2) & 31;

    float s[4] = {}, t[4] = {};
#pragma unroll
    for (int it = 0; it < 16; it++) {
        int cc = cg + it * 32;
        float4 v = *(const float4*)(res + (size_t)cc * (BDIM * PDIM) + orow0 + rg * 4);
        sres[(rg * 4 + 0) * LNPAD + cc] = v.x;  s[0] += v.x;  t[0] += v.x * v.x;
        sres[(rg * 4 + 1) * LNPAD + cc] = v.y;  s[1] += v.y;  t[1] += v.y * v.y;
        sres[(rg * 4 + 2) * LNPAD + cc] = v.z;  s[2] += v.z;  t[2] += v.z * v.z;
        sres[(rg * 4 + 3) * LNPAD + cc] = v.w;  s[3] += v.w;  t[3] += v.w * v.w;
    }
#pragma unroll
    for (int j = 0; j < 4; j++) {
        psum[rg * 4 + j][cg] = s[j];
        psqs[rg * 4 + j][cg] = t[j];
    }
    __syncthreads();

    if (threadIdx.x < LNROWS) {
        float S = 0.f, SS = 0.f;
#pragma unroll
        for (int g = 0; g < 32; g++) { S += psum[threadIdx.x][g]; SS += psqs[threadIdx.x][g]; }
        float mean = S * (1.0f / 512.0f);
        float var  = SS * (1.0f / 512.0f) - mean * mean;
        pmean[threadIdx.x] = mean;
        pinv[threadIdx.x]  = rsqrtf(var + 1e-5f);
    }
    __syncthreads();

    const size_t obase = (size_t)orow0 * CDIM;
    for (int i = threadIdx.x; i < LNROWS * 128; i += 256) {
        int q = i >> 7, cw = i & 127;
        float4 v = *(const float4*)(&sres[q * LNPAD + cw * 4]);
        float4 g = *(const float4*)(gamma + cw * 4);
        float4 bt = *(const float4*)(beta + cw * 4);
        float m = pmean[q], inv = pinv[q];
        float4 o4;
        o4.x = (v.x - m) * inv * g.x + bt.x;
        o4.y = (v.y - m) * inv * g.y + bt.y;
        o4.z = (v.z - m) * inv * g.z + bt.z;
        o4.w = (v.w - m) * inv * g.w + bt.w;
        *(float4*)(out + obase + (size_t)q * CDIM + cw * 4) = o4;
    }
}

// ---------------------------------------------------------------------------
extern "C" void kernel_launch(void* const* d_in, const int* in_sizes, int n_in,
                              void* d_out, int out_size)
{
    const float* x     = (const float*)d_in[0];
    const float* W1    = (const float*)d_in[1];
    const float* b1    = (const float*)d_in[2];
    const float* W2    = (const float*)d_in[3];
    const float* b2    = (const float*)d_in[4];
    const float* gamma = (const float*)d_in[5];
    const float* beta  = (const float*)d_in[6];
    float* out = (float*)d_out;

    __nv_bfloat16 *xh, *xl, *w1h, *w1l, *w2h, *w2l;
    float* resbuf;
    cudaGetSymbolAddress((void**)&xh, g_xh);
    cudaGetSymbolAddress((void**)&xl, g_xl);
    cudaGetSymbolAddress((void**)&resbuf, g_res);
    cudaGetSymbolAddress((void**)&w1h, g_w1h);
    cudaGetSymbolAddress((void**)&w1l, g_w1l);
    cudaGetSymbolAddress((void**)&w2h, g_w2h);
    cudaGetSymbolAddress((void**)&w2l, g_w2l);

    const int SMEM_FUSED = 74240;
    const int SMEM_LN = LNROWS * LNPAD * 4;   // 67072
    cudaFuncSetAttribute(fused_gemm_kernel, cudaFuncAttributeMaxDynamicSharedMemorySize, SMEM_FUSED);
    cudaFuncSetAttribute(ln_kernel, cudaFuncAttributeMaxDynamicSharedMemorySize, SMEM_LN);

    wsplit_kernel<<<(CDIM * PDIM * PDIM) / (256 * 8), 256>>>(W1, W2, w1h, w1l, w2h, w2l);
    xsplit_kernel<<<dim3(CDIM / 32, BDIM / 4), 256>>>(x, xh, xl);
    fused_gemm_kernel<<<dim3(BDIM / 128, CDIM), 256, SMEM_FUSED>>>(
        xh, xl, w1h, w1l, w2h, w2l, b1, b2, resbuf);
    ln_kernel<<<dim3(PDIM / LNROWS, BDIM), 256, SMEM_LN>>>(resbuf, gamma, beta, out);
}